// round 11
// baseline (speedup 1.0000x reference)
#include <cuda_runtime.h>
#include <cuda_fp16.h>
#include <cstdint>
#include <math.h>

#define BDIM 4
#define TDIM 1024
#define CDIM 2048
#define HDIM 16
#define DHEAD 128
#define RLORA 16

// ---------------- scratch (static device globals; no allocation) ----------------
__device__ float g_q[BDIM * TDIM * CDIM];
__device__ float g_k[BDIM * TDIM * CDIM];
__device__ float g_v[BDIM * TDIM * CDIM];
__device__ float g_xa[4 * BDIM * TDIM * RLORA];

__device__ __half g_xhi[BDIM * TDIM * CDIM];
__device__ __half g_xlo[BDIM * TDIM * CDIM];
__device__ __half g_yhi[BDIM * TDIM * CDIM];
__device__ __half g_ylo[BDIM * TDIM * CDIM];
__device__ __half g_wh[4 * CDIM * CDIM];        // W rounded once to fp16

// head-major fp16 attention operands
__device__ __half g_qhi[BDIM * HDIM * TDIM * DHEAD];
__device__ __half g_qlo[BDIM * HDIM * TDIM * DHEAD];
__device__ __half g_kh[BDIM * HDIM * TDIM * DHEAD];
__device__ __half g_vth[BDIM * HDIM * DHEAD * TDIM];   // [b,h,d,t]

// ======================= helpers =======================
__device__ __forceinline__ uint32_t smem_u32(const void* p) {
    uint32_t a;
    asm("{ .reg .u64 t; cvta.to.shared.u64 t, %1; cvt.u32.u64 %0, t; }"
        : "=r"(a) : "l"(p));
    return a;
}

#define CP_ASYNC16(dst, src) \
    asm volatile("cp.async.cg.shared.global [%0], [%1], 16;" :: "r"(dst), "l"(src))
#define CP_COMMIT() asm volatile("cp.async.commit_group;" ::: "memory")
#define CP_WAIT(n)  asm volatile("cp.async.wait_group %0;" :: "n"(n) : "memory")

__device__ __forceinline__ void ldsm4(uint32_t* r, uint32_t addr) {
    asm volatile("ldmatrix.sync.aligned.m8n8.x4.shared.b16 {%0,%1,%2,%3}, [%4];"
        : "=r"(r[0]), "=r"(r[1]), "=r"(r[2]), "=r"(r[3]) : "r"(addr));
}

__device__ __forceinline__ uint32_t lds32(uint32_t a) {
    uint32_t v;
    asm volatile("ld.shared.b32 %0, [%1];" : "=r"(v) : "r"(a));
    return v;
}

__device__ __forceinline__ void mma_f16(float* d, const uint32_t* a,
                                        uint32_t b0, uint32_t b1) {
    asm volatile("mma.sync.aligned.m16n8k16.row.col.f32.f16.f16.f32 "
        "{%0,%1,%2,%3}, {%4,%5,%6,%7}, {%8,%9}, {%0,%1,%2,%3};"
        : "+f"(d[0]), "+f"(d[1]), "+f"(d[2]), "+f"(d[3])
        : "r"(a[0]), "r"(a[1]), "r"(a[2]), "r"(a[3]), "r"(b0), "r"(b1));
}

__device__ __forceinline__ float ex2(float x) {
    float y;
    asm("ex2.approx.f32 %0, %1;" : "=f"(y) : "f"(x));
    return y;
}

// pack two f32 into f16x2; .x (lower) = lo_arg, .y (upper) = hi_arg
__device__ __forceinline__ uint32_t pack_h(float hi, float lo) {
    uint32_t r;
    asm("cvt.rn.f16x2.f32 %0, %1, %2;" : "=r"(r) : "f"(hi), "f"(lo));
    return r;
}

// ======================= split fp32 -> fp16 hi/lo =======================
__global__ void split_kernel(const float* __restrict__ s,
                             __half* __restrict__ hi,
                             __half* __restrict__ lo, int n4) {
    int i = blockIdx.x * blockDim.x + threadIdx.x;
    if (i >= n4) return;
    float4 v = ((const float4*)s)[i];
    __half h0 = __float2half_rn(v.x);
    __half h1 = __float2half_rn(v.y);
    __half h2 = __float2half_rn(v.z);
    __half h3 = __float2half_rn(v.w);
    __half l0 = __float2half_rn(v.x - __half2float(h0));
    __half l1 = __float2half_rn(v.y - __half2float(h1));
    __half l2 = __float2half_rn(v.z - __half2float(h2));
    __half l3 = __float2half_rn(v.w - __half2float(h3));
    ((__half2*)hi)[2 * i]     = __halves2half2(h0, h1);
    ((__half2*)hi)[2 * i + 1] = __halves2half2(h2, h3);
    ((__half2*)lo)[2 * i]     = __halves2half2(l0, l1);
    ((__half2*)lo)[2 * i + 1] = __halves2half2(l2, l3);
}

// ======================= round 4 weight matrices fp32 -> fp16 ==============
__global__ void round_all_kernel(const float* __restrict__ w0,
                                 const float* __restrict__ w1,
                                 const float* __restrict__ w2,
                                 const float* __restrict__ w3,
                                 __half* __restrict__ dst, int n4) {
    int i = blockIdx.x * blockDim.x + threadIdx.x;
    if (i >= n4) return;
    int wsel = blockIdx.y;
    const float* s = (wsel == 0) ? w0 : (wsel == 1) ? w1 : (wsel == 2) ? w2 : w3;
    __half* hi = dst + (size_t)wsel * CDIM * CDIM;
    float4 v = ((const float4*)s)[i];
    ((__half2*)hi)[2 * i]     = __floats2half2_rn(v.x, v.y);
    ((__half2*)hi)[2 * i + 1] = __floats2half2_rn(v.z, v.w);
}

// ======================= low-rank xA (fp32 input, up to 3 chunks) ==========
__global__ __launch_bounds__(256) void lowrank_kernel(
    const float* __restrict__ inp, const float* __restrict__ delta,
    int c0, int c1, int c2, int nc,
    float* __restrict__ o0, float* __restrict__ o1, float* __restrict__ o2) {
    __shared__ float xs[32 * 68];
    __shared__ float das[48 * 65];
    int tid = threadIdx.x;
    int row0 = blockIdx.x * 32;
    int b = row0 >> 10;
    int ty = tid >> 4, tx = tid & 15;
    int chunks[3] = {c0, c1, c2};

    float acc[2][3];
#pragma unroll
    for (int i = 0; i < 2; i++)
#pragma unroll
        for (int c = 0; c < 3; c++) acc[i][c] = 0.f;

    for (int k0 = 0; k0 < CDIM; k0 += 64) {
        __syncthreads();
        for (int i = tid; i < 32 * 16; i += 256) {
            int row = i >> 4, c4 = (i & 15) << 2;
            float4 v = *(const float4*)(inp + (size_t)(row0 + row) * CDIM + k0 + c4);
            *(float4*)&xs[row * 68 + c4] = v;
        }
        for (int i = tid; i < nc * 16 * 64; i += 256) {
            int r48 = i >> 6, kk = i & 63;
            int c = r48 >> 4, r = r48 & 15;
            das[r48 * 65 + kk] =
                delta[((size_t)b * 128 + (size_t)chunks[c] * 16 + r) * CDIM + k0 + kk];
        }
        __syncthreads();
#pragma unroll 8
        for (int kk = 0; kk < 64; kk++) {
            float a0 = xs[ty * 68 + kk];
            float a1 = xs[(ty + 16) * 68 + kk];
#pragma unroll
            for (int c = 0; c < 3; c++) {
                if (c < nc) {
                    float bb = das[(c * 16 + tx) * 65 + kk];
                    acc[0][c] += a0 * bb;
                    acc[1][c] += a1 * bb;
                }
            }
        }
    }
    float* outs[3] = {o0, o1, o2};
#pragma unroll
    for (int c = 0; c < 3; c++) {
        if (c < nc) {
            outs[c][(size_t)(row0 + ty) * RLORA + tx] = acc[0][c];
            outs[c][(size_t)(row0 + ty + 16) * RLORA + tx] = acc[1][c];
        }
    }
}

// ======================= low-rank xA (fp16 hi/lo input, 1 chunk) ===========
__global__ __launch_bounds__(256) void lowrank_h_kernel(
    const __half* __restrict__ hi, const __half* __restrict__ lo,
    const float* __restrict__ delta, int chunk, float* __restrict__ out) {
    __shared__ float xs[32 * 68];
    __shared__ float das[16 * 65];
    int tid = threadIdx.x;
    int row0 = blockIdx.x * 32;
    int b = row0 >> 10;
    int ty = tid >> 4, tx = tid & 15;

    float acc0 = 0.f, acc1 = 0.f;

    for (int k0 = 0; k0 < CDIM; k0 += 64) {
        __syncthreads();
        for (int i = tid; i < 32 * 16; i += 256) {
            int row = i >> 4, c4 = (i & 15) << 2;
            size_t base = (size_t)(row0 + row) * CDIM + k0 + c4;
            uint2 hv = *(const uint2*)(hi + base);
            uint2 lv = *(const uint2*)(lo + base);
            __half2 h0 = *(__half2*)&hv.x, h1 = *(__half2*)&hv.y;
            __half2 l0 = *(__half2*)&lv.x, l1 = *(__half2*)&lv.y;
            xs[row * 68 + c4 + 0] = __half2float(h0.x) + __half2float(l0.x);
            xs[row * 68 + c4 + 1] = __half2float(h0.y) + __half2float(l0.y);
            xs[row * 68 + c4 + 2] = __half2float(h1.x) + __half2float(l1.x);
            xs[row * 68 + c4 + 3] = __half2float(h1.y) + __half2float(l1.y);
        }
        for (int i = tid; i < 16 * 64; i += 256) {
            int r = i >> 6, kk = i & 63;
            das[r * 65 + kk] =
                delta[((size_t)b * 128 + (size_t)chunk * 16 + r) * CDIM + k0 + kk];
        }
        __syncthreads();
#pragma unroll 8
        for (int kk = 0; kk < 64; kk++) {
            float bb = das[tx * 65 + kk];
            acc0 += xs[ty * 68 + kk] * bb;
            acc1 += xs[(ty + 16) * 68 + kk] * bb;
        }
    }
    out[(size_t)(row0 + ty) * RLORA + tx] = acc0;
    out[(size_t)(row0 + ty + 16) * RLORA + tx] = acc1;
}

// ======================= mma.sync fp16 GEMM, 2-term, 2 CTAs/SM ============
// CTA tile 128x128, warp tile 32x64, GBK=64, double buffered.
// Two-pass mma issue: all hi-term (16 distinct accs) then all lo-term.
#define GBM 128
#define GBN 128
#define GBK 64
#define GNKT (CDIM / GBK)          // 32 k-tiles
#define SROW 144                   // 64 fp16 = 128B + 16B pad
#define ATILE_B (128 * SROW)       // 18432
#define BTILE_B (128 * SROW)       // 18432
#define OFF_ALO ATILE_B
#define OFF_B   (2 * ATILE_B)
#define STAGE_BYTES (2 * ATILE_B + BTILE_B)       // 55296
#define GEMM_SMEM (2 * STAGE_BYTES)               // 110592 -> 2 CTAs/SM

__global__ __launch_bounds__(256, 2) void gemm_tc_kernel(
    const __half* __restrict__ Ahi, const __half* __restrict__ Alo,
    const __half* __restrict__ Bh,
    const float* __restrict__ xA, const float* __restrict__ delta, int chunkB,
    float* __restrict__ out) {
    extern __shared__ char sm[];
    uint32_t sbase = smem_u32(sm);

    int tid = threadIdx.x;
    int warp = tid >> 5, lane = tid & 31;
    int b = blockIdx.z;
    int m0 = blockIdx.y * GBM;
    int n0 = blockIdx.x * GBN;
    const size_t Aoff = (size_t)(b * TDIM + m0) * CDIM;
    const size_t Boff = (size_t)n0 * CDIM;

    int wm = warp >> 1;   // 0..3 -> 32-row block
    int wn = warp & 1;    // 0..1 -> 64-col block

    float acc[2][8][4];
#pragma unroll
    for (int mt = 0; mt < 2; mt++)
#pragma unroll
        for (int nt = 0; nt < 8; nt++)
#pragma unroll
            for (int i = 0; i < 4; i++) acc[mt][nt][i] = 0.f;

    // loader: 3072 16B chunks per k-tile (Ahi 1024, Alo 1024, B 1024)
    auto issue_loads = [&](int kt, int buf) {
        int kk = kt * GBK;
        uint32_t sb = sbase + buf * STAGE_BYTES;
#pragma unroll
        for (int it = 0; it < 12; it++) {
            int i = tid + it * 256;
            const __half* gp;
            uint32_t dst;
            if (i < 2048) {
                int row = (i & 1023) >> 3, c = i & 7;
                gp = ((i < 1024) ? Ahi : Alo) + Aoff + (size_t)row * CDIM + kk + c * 8;
                dst = sb + ((i < 1024) ? 0 : OFF_ALO) + row * SROW + c * 16;
            } else {
                int j = i - 2048;
                int row = j >> 3, c = j & 7;
                gp = Bh + Boff + (size_t)row * CDIM + kk + c * 8;
                dst = sb + OFF_B + row * SROW + c * 16;
            }
            CP_ASYNC16(dst, gp);
        }
        CP_COMMIT();
    };

    issue_loads(0, 0);

    int a_r = lane & 15;
    int a_c = (lane >> 4) * 16;
    int b_r = (lane & 7) + ((lane >> 4) << 3);
    int b_c = ((lane >> 3) & 1) << 4;

    for (int kt = 0; kt < GNKT; kt++) {
        int buf = kt & 1;
        if (kt + 1 < GNKT) {
            issue_loads(kt + 1, buf ^ 1);
            CP_WAIT(1);
        } else {
            CP_WAIT(0);
        }
        __syncthreads();

        uint32_t sA_hi = sbase + buf * STAGE_BYTES + (wm * 32) * SROW;
        uint32_t sA_lo = sA_hi + OFF_ALO;
        uint32_t sB = sbase + buf * STAGE_BYTES + OFF_B + (wn * 64) * SROW;

#pragma unroll
        for (int ks = 0; ks < 4; ks++) {
            int kb = ks * 32;
            uint32_t ahi[2][4], alo[2][4], bbr[4][4];
#pragma unroll
            for (int mt = 0; mt < 2; mt++) {
                ldsm4(ahi[mt], sA_hi + (mt * 16 + a_r) * SROW + kb + a_c);
                ldsm4(alo[mt], sA_lo + (mt * 16 + a_r) * SROW + kb + a_c);
            }
#pragma unroll
            for (int np = 0; np < 4; np++)
                ldsm4(bbr[np], sB + (np * 16 + b_r) * SROW + kb + b_c);

            // pass 1: hi-term, 16 mmas to 16 distinct accumulators
#pragma unroll
            for (int np = 0; np < 4; np++)
#pragma unroll
                for (int mt = 0; mt < 2; mt++)
#pragma unroll
                    for (int h = 0; h < 2; h++)
                        mma_f16(acc[mt][np * 2 + h], ahi[mt],
                                bbr[np][2 * h], bbr[np][2 * h + 1]);
            // pass 2: lo-term
#pragma unroll
            for (int np = 0; np < 4; np++)
#pragma unroll
                for (int mt = 0; mt < 2; mt++)
#pragma unroll
                    for (int h = 0; h < 2; h++)
                        mma_f16(acc[mt][np * 2 + h], alo[mt],
                                bbr[np][2 * h], bbr[np][2 * h + 1]);
        }
        __syncthreads();
    }

    // ---- LoRA epilogue: load operands into reused stage memory ----
    float* xas = (float*)sm;                 // [128][16]
    float* dBs = xas + 128 * 16;             // [16][132]
    {
        const float4* xp = (const float4*)(xA + (size_t)(b * TDIM + m0) * RLORA);
        for (int i = tid; i < 128 * 4; i += 256) ((float4*)xas)[i] = xp[i];
        const float* dBg = delta + ((size_t)b * 128 + (size_t)chunkB * RLORA) * CDIM;
        for (int i = tid; i < 16 * 128; i += 256) {
            int r = i >> 7, c = i & 127;
            dBs[r * 132 + c] = dBg[(size_t)r * CDIM + n0 + c];
        }
    }
    __syncthreads();

    int rbase = wm * 32 + (lane >> 2);
    int cbase = wn * 64 + (lane & 3) * 2;
#pragma unroll
    for (int r = 0; r < RLORA; r++) {
        float xv[4];
#pragma unroll
        for (int m8 = 0; m8 < 4; m8++) xv[m8] = xas[(rbase + m8 * 8) * 16 + r];
#pragma unroll
        for (int nt = 0; nt < 8; nt++) {
            float b0 = dBs[r * 132 + cbase + nt * 8];
            float b1 = dBs[r * 132 + cbase + nt * 8 + 1];
#pragma unroll
            for (int mt = 0; mt < 2; mt++) {
                acc[mt][nt][0] += xv[2 * mt] * b0;
                acc[mt][nt][1] += xv[2 * mt] * b1;
                acc[mt][nt][2] += xv[2 * mt + 1] * b0;
                acc[mt][nt][3] += xv[2 * mt + 1] * b1;
            }
        }
    }

    // ---- store ----
#pragma unroll
    for (int mt = 0; mt < 2; mt++) {
        int row = m0 + wm * 32 + mt * 16 + (lane >> 2);
#pragma unroll
        for (int nt = 0; nt < 8; nt++) {
            int col = n0 + wn * 64 + nt * 8 + (lane & 3) * 2;
            float* p0 = out + (size_t)(b * TDIM + row) * CDIM + col;
            float* p1 = out + (size_t)(b * TDIM + row + 8) * CDIM + col;
            *(float2*)p0 = make_float2(acc[mt][nt][0], acc[mt][nt][1]);
            *(float2*)p1 = make_float2(acc[mt][nt][2], acc[mt][nt][3]);
        }
    }
}

// ======================= RoPE + convert to head-major fp16 ===========
__global__ void rope_convert_kernel(const float* __restrict__ q,
                                    const float* __restrict__ k,
                                    __half* __restrict__ qhi,
                                    __half* __restrict__ qlo,
                                    __half* __restrict__ kh) {
    int idx = blockIdx.x * blockDim.x + threadIdx.x;
    if (idx >= BDIM * HDIM * TDIM * 32) return;
    int d2p = idx & 31;
    int t = (idx >> 5) & 1023;
    int h = (idx >> 15) & 15;
    int b = idx >> 19;
    const float SCALE = 0.08838834764831845f;

    size_t inb = ((size_t)(b * TDIM + t)) * CDIM + h * DHEAD + 2 * d2p;
    size_t ob = (((size_t)(b * HDIM + h)) * TDIM + t) * DHEAD + 2 * d2p;

    float rq[2][2], rk[2][2];
#pragma unroll
    for (int e = 0; e < 2; e++) {
        int d2 = 2 * d2p + e;
        float inv = powf(10000.0f, -(float)d2 * (1.0f / 64.0f));
        float s, c;
        sincosf((float)t * inv, &s, &c);
        float ql = q[inb + e], qh2 = q[inb + e + 64];
        rq[e][0] = (ql * c - qh2 * s) * SCALE;
        rq[e][1] = (qh2 * c + ql * s) * SCALE;
        float kl = k[inb + e], kh2 = k[inb + e + 64];
        rk[e][0] = kl * c - kh2 * s;
        rk[e][1] = kh2 * c + kl * s;
    }
#pragma unroll
    for (int half = 0; half < 2; half++) {
        float a = rq[0][half], bb = rq[1][half];
        uint32_t hi = pack_h(bb, a);
        __half2 hv = *(__half2*)&hi;
        float la = a - __half2float(hv.x);
        float lb = bb - __half2float(hv.y);
        uint32_t lo = pack_h(lb, la);
        *(uint32_t*)(qhi + ob + half * 64) = hi;
        *(uint32_t*)(qlo + ob + half * 64) = lo;

        *(uint32_t*)(kh + ob + half * 64) = pack_h(rk[1][half], rk[0][half]);
    }
}

// ======================= V transpose to [b,h,d,t] fp16 ===============
__global__ __launch_bounds__(256) void vtrans_kernel(const float* __restrict__ v,
                                                     __half* __restrict__ vth) {
    __shared__ float vs[64 * 132];
    int t0 = blockIdx.x * 64;
    int h = blockIdx.y, b = blockIdx.z;
    int tid = threadIdx.x;

#pragma unroll
    for (int it = 0; it < 8; it++) {
        int i4 = tid + it * 256;
        int row = i4 >> 5, c = (i4 & 31) << 2;
        float4 val = *(const float4*)(v + ((size_t)(b * TDIM + t0 + row)) * CDIM + h * DHEAD + c);
        *(float4*)&vs[row * 132 + c] = val;
    }
    __syncthreads();

    size_t obase = ((size_t)(b * HDIM + h)) * DHEAD * TDIM;
#pragma unroll
    for (int it = 0; it < 16; it++) {
        int j = tid + it * 256;
        int d = j >> 5, tp = j & 31;
        float a = vs[(2 * tp) * 132 + d];
        float bb = vs[(2 * tp + 1) * 132 + d];
        *(uint32_t*)(vth + obase + (size_t)d * TDIM + t0 + 2 * tp) = pack_h(bb, a);
    }
}

// ======================= tensor-core flash attention (fp16, 2-term) =======
// Q tile 64 rows/CTA, 128 threads (4 warps x 16 rows), 2 CTAs/SM.
// Two-pass mma issue in both QK and PV loops.
#define AQ_STRIDE 272
#define KT_STRIDE 272
#define VT_STRIDE 144
#define AQ_TILE (64 * AQ_STRIDE)      // 17408
#define KT_TILE (64 * KT_STRIDE)      // 17408
#define VT_TILE (128 * VT_STRIDE)     // 18432
#define KV_BUF (KT_TILE + VT_TILE)    // 35840
#define ATTN_SMEM (2 * AQ_TILE + 2 * KV_BUF)   // 106496 -> 2 CTAs/SM

__global__ __launch_bounds__(128, 2)
void attn_tc_kernel(const __half* __restrict__ qhi,
                    const __half* __restrict__ qlo,
                    const __half* __restrict__ kh,
                    const __half* __restrict__ vth,
                    __half* __restrict__ yhi,
                    __half* __restrict__ ylo) {
    extern __shared__ char sm[];
    uint32_t sbase = smem_u32(sm);

    int tid = threadIdx.x;
    int warp = tid >> 5, lane = tid & 31;
    int b = blockIdx.z, h = blockIdx.y;
    int t0 = blockIdx.x * 64;

    const size_t qoff = (((size_t)(b * HDIM + h)) * TDIM + t0) * DHEAD;
    const size_t koff = ((size_t)(b * HDIM + h)) * TDIM * DHEAD;
    const size_t voff = ((size_t)(b * HDIM + h)) * DHEAD * TDIM;

    // Q hi+lo: 2048 chunks, 128 threads -> 16 iters
#pragma unroll
    for (int it = 0; it < 16; it++) {
        int i = tid + it * 128;
        int tensor = i >> 10;
        int rem = i & 1023;
        int row = rem >> 4, ch = rem & 15;
        const __half* src = (tensor ? qlo : qhi) + qoff + (size_t)row * DHEAD + ch * 8;
        CP_ASYNC16(sbase + tensor * AQ_TILE + row * AQ_STRIDE + ch * 16, src);
    }
    CP_COMMIT();

    auto issue_kv = [&](int kt, int buf) {
        int s0 = kt * 64;
        uint32_t kb = sbase + 2 * AQ_TILE + buf * KV_BUF;
#pragma unroll
        for (int it = 0; it < 16; it++) {
            int i = tid + it * 128;       // 0..2047
            if (i < 1024) {
                int row = i >> 4, ch = i & 15;
                const __half* src = kh + koff + (size_t)(s0 + row) * DHEAD + ch * 8;
                CP_ASYNC16(kb + row * KT_STRIDE + ch * 16, src);
            } else {
                int j = i - 1024;
                int row = j >> 3, ch = j & 7;
                const __half* src = vth + voff + (size_t)row * TDIM + s0 + ch * 8;
                CP_ASYNC16(kb + KT_TILE + row * VT_STRIDE + ch * 16, src);
            }
        }
        CP_COMMIT();
    };

    issue_kv(0, 0);

    int wrow = warp * 16;
    int qr = lane >> 2;
    int qc4 = (lane & 3) * 4;
    const float L2E = 1.4426950408889634f;

    float o[16][4];
#pragma unroll
    for (int nt = 0; nt < 16; nt++)
#pragma unroll
        for (int i = 0; i < 4; i++) o[nt][i] = 0.f;
    float m0 = -1e30f, m1 = -1e30f, l0 = 0.f, l1 = 0.f;

    for (int kt = 0; kt < TDIM / 64; kt++) {
        int buf = kt & 1;
        if (kt + 1 < TDIM / 64) {
            issue_kv(kt + 1, buf ^ 1);
            CP_WAIT(1);
        } else {
            CP_WAIT(0);
        }
        __syncthreads();

        uint32_t kvb = sbase + 2 * AQ_TILE + buf * KV_BUF;
        uint32_t k_s = kvb;
        uint32_t v_s = kvb + KT_TILE;

        float c[8][4];
#pragma unroll
        for (int nt = 0; nt < 8; nt++)
#pragma unroll
            for (int i = 0; i < 4; i++) c[nt][i] = 0.f;

#pragma unroll
        for (int ks = 0; ks < 8; ks++) {
            int kb = ks * 32;
            uint32_t ah[4], al[4], kfr[8][2];
            uint32_t qa = sbase + (wrow + qr) * AQ_STRIDE + kb + qc4;
            ah[0] = lds32(qa);           ah[1] = lds32(qa + 8 * AQ_STRIDE);
            ah[2] = lds32(qa + 16);      ah[3] = lds32(qa + 8 * AQ_STRIDE + 16);
            uint32_t qb = qa + AQ_TILE;
            al[0] = lds32(qb);           al[1] = lds32(qb + 8 * AQ_STRIDE);
            al[2] = lds32(qb + 16);      al[3] = lds32(qb + 8 * AQ_STRIDE + 16);
#pragma unroll
            for (int nt = 0; nt < 8; nt++) {
                uint32_t ka = k_s + (nt * 8 + qr) * KT_STRIDE + kb + qc4;
                kfr[nt][0] = lds32(ka); kfr[nt][1] = lds32(ka + 16);
            }
            // pass 1: hi-term over 8 distinct accumulators
#pragma unroll
            for (int nt = 0; nt < 8; nt++)
                mma_f16(c[nt], ah, kfr[nt][0], kfr[nt][1]);
            // pass 2: lo-term
#pragma unroll
            for (int nt = 0; nt < 8; nt++)
                mma_f16(c[nt], al, kfr[nt][0], kfr[nt][1]);
        }

        float rm0 = -1e30f, rm1 = -1e30f;
#pragma unroll
        for (int nt = 0; nt < 8; nt++) {
            rm0 = fmaxf(rm0, fmaxf(c[nt][0], c[nt][1]));
            rm1 = fmaxf(rm1, fmaxf(c[nt][2], c[nt][3]));
        }
        rm0 = fmaxf(rm0, __shfl_xor_sync(0xffffffffu, rm0, 1));
        rm0 = fmaxf(rm0, __shfl_xor_sync(0xffffffffu, rm0, 2));
        rm1 = fmaxf(rm1, __shfl_xor_sync(0xffffffffu, rm1, 1));
        rm1 = fmaxf(rm1, __shfl_xor_sync(0xffffffffu, rm1, 2));
        float mn0 = fmaxf(m0, rm0), mn1 = fmaxf(m1, rm1);
        float cf0 = ex2((m0 - mn0) * L2E), cf1 = ex2((m1 - mn1) * L2E);
        m0 = mn0; m1 = mn1;
        float rs0 = 0.f, rs1 = 0.f;
#pragma unroll
        for (int nt = 0; nt < 8; nt++) {
            c[nt][0] = ex2((c[nt][0] - m0) * L2E);
            c[nt][1] = ex2((c[nt][1] - m0) * L2E);
            c[nt][2] = ex2((c[nt][2] - m1) * L2E);
            c[nt][3] = ex2((c[nt][3] - m1) * L2E);
            rs0 += c[nt][0] + c[nt][1];
            rs1 += c[nt][2] + c[nt][3];
        }
        rs0 += __shfl_xor_sync(0xffffffffu, rs0, 1);
        rs0 += __shfl_xor_sync(0xffffffffu, rs0, 2);
        rs1 += __shfl_xor_sync(0xffffffffu, rs1, 1);
        rs1 += __shfl_xor_sync(0xffffffffu, rs1, 2);
        l0 = l0 * cf0 + rs0;
        l1 = l1 * cf1 + rs1;
#pragma unroll
        for (int nt = 0; nt < 16; nt++) {
            o[nt][0] *= cf0; o[nt][1] *= cf0;
            o[nt][2] *= cf1; o[nt][3] *= cf1;
        }

        uint32_t phi[8][2], plo[8][2];
#pragma unroll
        for (int nt = 0; nt < 8; nt++) {
            uint32_t h0 = pack_h(c[nt][1], c[nt][0]);
            uint32_t h1 = pack_h(c[nt][3], c[nt][2]);
            phi[nt][0] = h0; phi[nt][1] = h1;
            __half2 v0 = *(__half2*)&h0;
            __half2 v1 = *(__half2*)&h1;
            float r0 = c[nt][0] - __half2float(v0.x);
            float r1 = c[nt][1] - __half2float(v0.y);
            float r2 = c[nt][2] - __half2float(v1.x);
            float r3 = c[nt][3] - __half2float(v1.y);
            plo[nt][0] = pack_h(r1, r0);
            plo[nt][1] = pack_h(r3, r2);
        }

#pragma unroll
        for (int ks2 = 0; ks2 < 4; ks2++) {
            uint32_t Ah[4] = {phi[2 * ks2][0], phi[2 * ks2][1],
                              phi[2 * ks2 + 1][0], phi[2 * ks2 + 1][1]};
            uint32_t Al[4] = {plo[2 * ks2][0], plo[2 * ks2][1],
                              plo[2 * ks2 + 1][0], plo[2 * ks2 + 1][1]};
            uint32_t vfr[16][2];
#pragma unroll
            for (int nt = 0; nt < 16; nt++) {
                uint32_t va = v_s + (nt * 8 + qr) * VT_STRIDE + ks2 * 32 + qc4;
                vfr[nt][0] = lds32(va); vfr[nt][1] = lds32(va + 16);
            }
            // pass 1: hi-term over 16 distinct accumulators
#pragma unroll
            for (int nt = 0; nt < 16; nt++)
                mma_f16(o[nt], Ah, vfr[nt][0], vfr[nt][1]);
            // pass 2: lo-term
#pragma unroll
            for (int nt = 0; nt < 16; nt++)
                mma_f16(o[nt], Al, vfr[nt][0], vfr[nt][1]);
        }
        __syncthreads();
    }

    // ---- normalize + write y directly as fp16 hi/lo [B,T,C] ----
    float linv0 = 1.f / l0, linv1 = 1.f / l1;
    int row = t0 + wrow + qr;
#pragma unroll
    for (int nt = 0; nt < 16; nt++) {
        int col = h * DHEAD + nt * 8 + (lane & 3) * 2;
        size_t i0 = ((size_t)(b * TDIM + row)) * CDIM + col;
        size_t i1 = ((size_t)(b * TDIM + row + 8)) * CDIM + col;

        float v0 = o[nt][0] * linv0, v1 = o[nt][1] * linv0;
        uint32_t hw = pack_h(v1, v0);
        __half2 hh = *(__half2*)&hw;
        uint32_t lw = pack_h(v1 - __half2float(hh.y), v0 - __half2float(hh.x));
        *(uint32_t*)(yhi + i0) = hw;
        *(uint32_t*)(ylo + i0) = lw;

        float v2 = o[nt][2] * linv1, v3 = o[nt][3] * linv1;
        uint32_t hw2 = pack_h(v3, v2);
        __half2 hh2 = *(__half2*)&hw2;
        uint32_t lw2 = pack_h(v3 - __half2float(hh2.y), v2 - __half2float(hh2.x));
        *(uint32_t*)(yhi + i1) = hw2;
        *(uint32_t*)(ylo + i1) = lw2;
    }
}

// ---------------- host ----------------
extern "C" void kernel_launch(void* const* d_in, const int* in_sizes, int n_in,
                              void* d_out, int out_size) {
    const float* x     = (const float*)d_in[0];
    const float* delta = (const float*)d_in[1];
    const float* Wq    = (const float*)d_in[2];
    const float* Wk    = (const float*)d_in[3];
    const float* Wv    = (const float*)d_in[4];
    const float* Wo    = (const float*)d_in[5];
    float* out = (float*)d_out;

    float *qp, *kp, *vp, *xap;
    __half *xhi, *xlo, *yhi, *ylo, *wh;
    __half *qhi, *qlo, *kh, *vth;
    cudaGetSymbolAddress((void**)&qp, g_q);
    cudaGetSymbolAddress((void**)&kp, g_k);
    cudaGetSymbolAddress((void**)&vp, g_v);
    cudaGetSymbolAddress((void**)&xap, g_xa);
    cudaGetSymbolAddress((void**)&xhi, g_xhi);
    cudaGetSymbolAddress((void**)&xlo, g_xlo);
    cudaGetSymbolAddress((void**)&yhi, g_yhi);
    cudaGetSymbolAddress((void**)&ylo, g_ylo);
    cudaGetSymbolAddress((void**)&wh, g_wh);
    cudaGetSymbolAddress((void**)&qhi, g_qhi);
    cudaGetSymbolAddress((void**)&qlo, g_qlo);
    cudaGetSymbolAddress((void**)&kh, g_kh);
    cudaGetSymbolAddress((void**)&vth, g_vth);

    const int BT = BDIM * TDIM;
    float* xaq = xap;
    float* xak = xap + 1 * BT * RLORA;
    float* xav = xap + 2 * BT * RLORA;
    float* xao = xap + 3 * BT * RLORA;

    cudaFuncSetAttribute(gemm_tc_kernel, cudaFuncAttributeMaxDynamicSharedMemorySize, GEMM_SMEM);
    cudaFuncSetAttribute(attn_tc_kernel, cudaFuncAttributeMaxDynamicSharedMemorySize, ATTN_SMEM);

    const int WN = CDIM * CDIM;
    const int XN = BDIM * TDIM * CDIM;

    // Launch order chosen so launch #6 (ncu -s 5 -c 1) is a gemm_tc_kernel.
    split_kernel<<<(XN / 4 + 255) / 256, 256>>>(x, xhi, xlo, XN / 4);                 // 1
    round_all_kernel<<<dim3((WN / 4 + 255) / 256, 4), 256>>>(Wq, Wk, Wv, Wo, wh, WN / 4); // 2
    lowrank_kernel<<<BT / 32, 256>>>(x, delta, 0, 2, 4, 3, xaq, xak, xav);            // 3

    dim3 gg(CDIM / GBN, TDIM / GBM, BDIM);
    gemm_tc_kernel<<<gg, 256, GEMM_SMEM>>>(xhi, xlo, wh + 0 * (size_t)WN, xaq, delta, 1, qp); // 4
    gemm_tc_kernel<<<gg, 256, GEMM_SMEM>>>(xhi, xlo, wh + 1 * (size_t)WN, xak, delta, 3, kp); // 5
    gemm_tc_kernel<<<gg, 256, GEMM_SMEM>>>(xhi, xlo, wh + 2 * (size_t)WN, xav, delta, 5, vp); // 6 <- profiled

    int rc_n = BDIM * HDIM * TDIM * 32;
    rope_convert_kernel<<<(rc_n + 255) / 256, 256>>>(qp, kp, qhi, qlo, kh);           // 7
    vtrans_kernel<<<dim3(TDIM / 64, HDIM, BDIM), 256>>>(vp, vth);                     // 8

    attn_tc_kernel<<<dim3(TDIM / 64, HDIM, BDIM), 128, ATTN_SMEM>>>(
        qhi, qlo, kh, vth, yhi, ylo);                                                 // 9

    lowrank_h_kernel<<<BT / 32, 256>>>(yhi, ylo, delta, 6, xao);                      // 10
    gemm_tc_kernel<<<gg, 256, GEMM_SMEM>>>(yhi, ylo, wh + 3 * (size_t)WN, xao, delta, 7, out); // 11
}

// round 12
// speedup vs baseline: 1.0180x; 1.0180x over previous
#include <cuda_runtime.h>
#include <cuda_fp16.h>
#include <cstdint>
#include <math.h>

#define BDIM 4
#define TDIM 1024
#define CDIM 2048
#define HDIM 16
#define DHEAD 128
#define RLORA 16

// ---------------- scratch (static device globals; no allocation) ----------------
__device__ float g_q[BDIM * TDIM * CDIM];
__device__ float g_k[BDIM * TDIM * CDIM];
__device__ float g_v[BDIM * TDIM * CDIM];
__device__ float g_xa[4 * BDIM * TDIM * RLORA];

__device__ __half g_xhi[BDIM * TDIM * CDIM];
__device__ __half g_xlo[BDIM * TDIM * CDIM];
__device__ __half g_yhi[BDIM * TDIM * CDIM];
__device__ __half g_ylo[BDIM * TDIM * CDIM];
__device__ __half g_wh[4 * CDIM * CDIM];   // W in mma B-fragment layout (per 16x16 block)

// head-major fp16 attention operands
__device__ __half g_qhi[BDIM * HDIM * TDIM * DHEAD];
__device__ __half g_qlo[BDIM * HDIM * TDIM * DHEAD];
__device__ __half g_kh[BDIM * HDIM * TDIM * DHEAD];
__device__ __half g_vth[BDIM * HDIM * DHEAD * TDIM];   // [b,h,d,t]

// ======================= helpers =======================
__device__ __forceinline__ uint32_t smem_u32(const void* p) {
    uint32_t a;
    asm("{ .reg .u64 t; cvta.to.shared.u64 t, %1; cvt.u32.u64 %0, t; }"
        : "=r"(a) : "l"(p));
    return a;
}

#define CP_ASYNC16(dst, src) \
    asm volatile("cp.async.cg.shared.global [%0], [%1], 16;" :: "r"(dst), "l"(src))
#define CP_COMMIT() asm volatile("cp.async.commit_group;" ::: "memory")
#define CP_WAIT(n)  asm volatile("cp.async.wait_group %0;" :: "n"(n) : "memory")

__device__ __forceinline__ void ldsm4(uint32_t* r, uint32_t addr) {
    asm volatile("ldmatrix.sync.aligned.m8n8.x4.shared.b16 {%0,%1,%2,%3}, [%4];"
        : "=r"(r[0]), "=r"(r[1]), "=r"(r[2]), "=r"(r[3]) : "r"(addr));
}

__device__ __forceinline__ uint32_t lds32(uint32_t a) {
    uint32_t v;
    asm volatile("ld.shared.b32 %0, [%1];" : "=r"(v) : "r"(a));
    return v;
}

__device__ __forceinline__ void mma_f16(float* d, const uint32_t* a,
                                        uint32_t b0, uint32_t b1) {
    asm volatile("mma.sync.aligned.m16n8k16.row.col.f32.f16.f16.f32 "
        "{%0,%1,%2,%3}, {%4,%5,%6,%7}, {%8,%9}, {%0,%1,%2,%3};"
        : "+f"(d[0]), "+f"(d[1]), "+f"(d[2]), "+f"(d[3])
        : "r"(a[0]), "r"(a[1]), "r"(a[2]), "r"(a[3]), "r"(b0), "r"(b1));
}

__device__ __forceinline__ float ex2(float x) {
    float y;
    asm("ex2.approx.f32 %0, %1;" : "=f"(y) : "f"(x));
    return y;
}

// pack two f32 into f16x2; .x (lower) = lo_arg, .y (upper) = hi_arg
__device__ __forceinline__ uint32_t pack_h(float hi, float lo) {
    uint32_t r;
    asm("cvt.rn.f16x2.f32 %0, %1, %2;" : "=r"(r) : "f"(hi), "f"(lo));
    return r;
}

// ======================= split fp32 -> fp16 hi/lo =======================
__global__ void split_kernel(const float* __restrict__ s,
                             __half* __restrict__ hi,
                             __half* __restrict__ lo, int n4) {
    int i = blockIdx.x * blockDim.x + threadIdx.x;
    if (i >= n4) return;
    float4 v = ((const float4*)s)[i];
    __half h0 = __float2half_rn(v.x);
    __half h1 = __float2half_rn(v.y);
    __half h2 = __float2half_rn(v.z);
    __half h3 = __float2half_rn(v.w);
    __half l0 = __float2half_rn(v.x - __half2float(h0));
    __half l1 = __float2half_rn(v.y - __half2float(h1));
    __half l2 = __float2half_rn(v.z - __half2float(h2));
    __half l3 = __float2half_rn(v.w - __half2float(h3));
    ((__half2*)hi)[2 * i]     = __halves2half2(h0, h1);
    ((__half2*)hi)[2 * i + 1] = __halves2half2(h2, h3);
    ((__half2*)lo)[2 * i]     = __halves2half2(l0, l1);
    ((__half2*)lo)[2 * i + 1] = __halves2half2(l2, l3);
}

// ===== round 4 weights fp32 -> fp16 in mma B-fragment layout =====
// Element (n, k) of W[n][k] goes to block (nb=n>>4, kb=k>>4):
//   lane = (n&7)*4 + ((k&7)>>1), ri = ((n>>3)&1)*2 + ((k&15)>=8), half = k&1
//   addr(halfs) = (nb*(CDIM/16)+kb)*256 + lane*8 + ri*2 + half
__global__ void round_all_kernel(const float* __restrict__ w0,
                                 const float* __restrict__ w1,
                                 const float* __restrict__ w2,
                                 const float* __restrict__ w3,
                                 __half* __restrict__ dst, int n4) {
    int i = blockIdx.x * blockDim.x + threadIdx.x;
    if (i >= n4) return;
    int wsel = blockIdx.y;
    const float* s = (wsel == 0) ? w0 : (wsel == 1) ? w1 : (wsel == 2) ? w2 : w3;
    __half* o = dst + (size_t)wsel * CDIM * CDIM;

    int n = i / (CDIM / 4);
    int kq = (i % (CDIM / 4)) * 4;          // kq % 4 == 0
    float4 v = ((const float4*)s)[i];
    uint32_t p0 = pack_h(v.y, v.x);         // k = kq, kq+1
    uint32_t p1 = pack_h(v.w, v.z);         // k = kq+2, kq+3

    int nb = n >> 4, kb = kq >> 4;
    int ri = (((n >> 3) & 1) << 1) | (((kq & 15) >= 8) ? 1 : 0);
    int lane0 = (n & 7) * 4 + ((kq & 7) >> 1);
    size_t blk = ((size_t)nb * (CDIM / 16) + kb) * 256;
    *(uint32_t*)(o + blk + lane0 * 8 + ri * 2) = p0;
    *(uint32_t*)(o + blk + (lane0 + 1) * 8 + ri * 2) = p1;
}

// ======================= low-rank xA (fp32 input, up to 3 chunks) ==========
__global__ __launch_bounds__(256) void lowrank_kernel(
    const float* __restrict__ inp, const float* __restrict__ delta,
    int c0, int c1, int c2, int nc,
    float* __restrict__ o0, float* __restrict__ o1, float* __restrict__ o2) {
    __shared__ float xs[32 * 68];
    __shared__ float das[48 * 65];
    int tid = threadIdx.x;
    int row0 = blockIdx.x * 32;
    int b = row0 >> 10;
    int ty = tid >> 4, tx = tid & 15;
    int chunks[3] = {c0, c1, c2};

    float acc[2][3];
#pragma unroll
    for (int i = 0; i < 2; i++)
#pragma unroll
        for (int c = 0; c < 3; c++) acc[i][c] = 0.f;

    for (int k0 = 0; k0 < CDIM; k0 += 64) {
        __syncthreads();
        for (int i = tid; i < 32 * 16; i += 256) {
            int row = i >> 4, c4 = (i & 15) << 2;
            float4 v = *(const float4*)(inp + (size_t)(row0 + row) * CDIM + k0 + c4);
            *(float4*)&xs[row * 68 + c4] = v;
        }
        for (int i = tid; i < nc * 16 * 64; i += 256) {
            int r48 = i >> 6, kk = i & 63;
            int c = r48 >> 4, r = r48 & 15;
            das[r48 * 65 + kk] =
                delta[((size_t)b * 128 + (size_t)chunks[c] * 16 + r) * CDIM + k0 + kk];
        }
        __syncthreads();
#pragma unroll 8
        for (int kk = 0; kk < 64; kk++) {
            float a0 = xs[ty * 68 + kk];
            float a1 = xs[(ty + 16) * 68 + kk];
#pragma unroll
            for (int c = 0; c < 3; c++) {
                if (c < nc) {
                    float bb = das[(c * 16 + tx) * 65 + kk];
                    acc[0][c] += a0 * bb;
                    acc[1][c] += a1 * bb;
                }
            }
        }
    }
    float* outs[3] = {o0, o1, o2};
#pragma unroll
    for (int c = 0; c < 3; c++) {
        if (c < nc) {
            outs[c][(size_t)(row0 + ty) * RLORA + tx] = acc[0][c];
            outs[c][(size_t)(row0 + ty + 16) * RLORA + tx] = acc[1][c];
        }
    }
}

// ======================= low-rank xA (fp16 hi/lo input, 1 chunk) ===========
__global__ __launch_bounds__(256) void lowrank_h_kernel(
    const __half* __restrict__ hi, const __half* __restrict__ lo,
    const float* __restrict__ delta, int chunk, float* __restrict__ out) {
    __shared__ float xs[32 * 68];
    __shared__ float das[16 * 65];
    int tid = threadIdx.x;
    int row0 = blockIdx.x * 32;
    int b = row0 >> 10;
    int ty = tid >> 4, tx = tid & 15;

    float acc0 = 0.f, acc1 = 0.f;

    for (int k0 = 0; k0 < CDIM; k0 += 64) {
        __syncthreads();
        for (int i = tid; i < 32 * 16; i += 256) {
            int row = i >> 4, c4 = (i & 15) << 2;
            size_t base = (size_t)(row0 + row) * CDIM + k0 + c4;
            uint2 hv = *(const uint2*)(hi + base);
            uint2 lv = *(const uint2*)(lo + base);
            __half2 h0 = *(__half2*)&hv.x, h1 = *(__half2*)&hv.y;
            __half2 l0 = *(__half2*)&lv.x, l1 = *(__half2*)&lv.y;
            xs[row * 68 + c4 + 0] = __half2float(h0.x) + __half2float(l0.x);
            xs[row * 68 + c4 + 1] = __half2float(h0.y) + __half2float(l0.y);
            xs[row * 68 + c4 + 2] = __half2float(h1.x) + __half2float(l1.x);
            xs[row * 68 + c4 + 3] = __half2float(h1.y) + __half2float(l1.y);
        }
        for (int i = tid; i < 16 * 64; i += 256) {
            int r = i >> 6, kk = i & 63;
            das[r * 65 + kk] =
                delta[((size_t)b * 128 + (size_t)chunk * 16 + r) * CDIM + k0 + kk];
        }
        __syncthreads();
#pragma unroll 8
        for (int kk = 0; kk < 64; kk++) {
            float bb = das[tx * 65 + kk];
            acc0 += xs[ty * 68 + kk] * bb;
            acc1 += xs[(ty + 16) * 68 + kk] * bb;
        }
    }
    out[(size_t)(row0 + ty) * RLORA + tx] = acc0;
    out[(size_t)(row0 + ty + 16) * RLORA + tx] = acc1;
}

// ======================= mma.sync fp16 GEMM, 2-term, 2 CTAs/SM ============
// CTA tile 128x128, warp tile 32x64, GBK=64.
// A (activations, hi+lo) via cp.async smem + ldsm, double buffered.
// B (weights) via direct LDG.128 of pre-permuted fragments, reg double buffer.
#define GBM 128
#define GBN 128
#define GBK 64
#define GNKT (CDIM / GBK)          // 32 k-tiles; 128 k-steps of 16
#define SROW 144
#define ATILE_B (128 * SROW)       // 18432
#define OFF_ALO ATILE_B
#define STAGE_BYTES (2 * ATILE_B)  // 36864
#define GEMM_SMEM (2 * STAGE_BYTES) // 73728 -> 2 CTAs/SM

__device__ __forceinline__ void ldgB(const __half* __restrict__ Wf, int nbC,
                                     int step, int lane, uint32_t* B) {
#pragma unroll
    for (int np = 0; np < 4; np++) {
        const uint4* p = (const uint4*)Wf +
            (((size_t)(nbC + np) * (CDIM / 16) + step) * 32 + lane);
        uint4 v = *p;
        B[np * 4 + 0] = v.x; B[np * 4 + 1] = v.y;
        B[np * 4 + 2] = v.z; B[np * 4 + 3] = v.w;
    }
}

__global__ __launch_bounds__(256, 2) void gemm_tc_kernel(
    const __half* __restrict__ Ahi, const __half* __restrict__ Alo,
    const __half* __restrict__ Wf,
    const float* __restrict__ xA, const float* __restrict__ delta, int chunkB,
    float* __restrict__ out) {
    extern __shared__ char sm[];
    uint32_t sbase = smem_u32(sm);

    int tid = threadIdx.x;
    int warp = tid >> 5, lane = tid & 31;
    int b = blockIdx.z;
    int m0 = blockIdx.y * GBM;
    int n0 = blockIdx.x * GBN;
    const size_t Aoff = (size_t)(b * TDIM + m0) * CDIM;

    int wm = warp >> 1;   // 0..3 -> 32-row block
    int wn = warp & 1;    // 0..1 -> 64-col block
    int nbC = (n0 >> 4) + wn * 4;

    float acc[2][8][4];
#pragma unroll
    for (int mt = 0; mt < 2; mt++)
#pragma unroll
        for (int nt = 0; nt < 8; nt++)
#pragma unroll
            for (int i = 0; i < 4; i++) acc[mt][nt][i] = 0.f;

    // A loader: 2048 16B chunks per k-tile (hi 1024 + lo 1024)
    auto issue_loads = [&](int kt, int buf) {
        int kk = kt * GBK;
        uint32_t sb = sbase + buf * STAGE_BYTES;
#pragma unroll
        for (int it = 0; it < 8; it++) {
            int i = tid + it * 256;
            int row = (i & 1023) >> 3, c = i & 7;
            const __half* gp = ((i < 1024) ? Ahi : Alo) + Aoff + (size_t)row * CDIM + kk + c * 8;
            uint32_t dst = sb + ((i < 1024) ? 0 : OFF_ALO) + row * SROW + c * 16;
            CP_ASYNC16(dst, gp);
        }
        CP_COMMIT();
    };

    issue_loads(0, 0);

    uint32_t Bc[16], Bn[16];
    ldgB(Wf, nbC, 0, lane, Bc);   // step 0

    int a_r = lane & 15;
    int a_c = (lane >> 4) * 16;

    for (int kt = 0; kt < GNKT; kt++) {
        int buf = kt & 1;
        if (kt + 1 < GNKT) {
            issue_loads(kt + 1, buf ^ 1);
            CP_WAIT(1);
        } else {
            CP_WAIT(0);
        }
        __syncthreads();

        uint32_t sA_hi = sbase + buf * STAGE_BYTES + (wm * 32) * SROW;
        uint32_t sA_lo = sA_hi + OFF_ALO;

#pragma unroll
        for (int ks = 0; ks < 4; ks++) {
            int step = kt * 4 + ks;
            uint32_t* Bu = (ks & 1) ? Bn : Bc;
            uint32_t* Bp = (ks & 1) ? Bc : Bn;
            if (step + 1 < GNKT * 4) ldgB(Wf, nbC, step + 1, lane, Bp);

            int kb = ks * 32;
            uint32_t ahi[2][4], alo[2][4];
#pragma unroll
            for (int mt = 0; mt < 2; mt++) {
                ldsm4(ahi[mt], sA_hi + (mt * 16 + a_r) * SROW + kb + a_c);
                ldsm4(alo[mt], sA_lo + (mt * 16 + a_r) * SROW + kb + a_c);
            }
            // hi pass (16 distinct accumulators), then lo pass
#pragma unroll
            for (int np = 0; np < 4; np++)
#pragma unroll
                for (int mt = 0; mt < 2; mt++)
#pragma unroll
                    for (int h = 0; h < 2; h++)
                        mma_f16(acc[mt][np * 2 + h], ahi[mt],
                                Bu[np * 4 + h * 2], Bu[np * 4 + h * 2 + 1]);
#pragma unroll
            for (int np = 0; np < 4; np++)
#pragma unroll
                for (int mt = 0; mt < 2; mt++)
#pragma unroll
                    for (int h = 0; h < 2; h++)
                        mma_f16(acc[mt][np * 2 + h], alo[mt],
                                Bu[np * 4 + h * 2], Bu[np * 4 + h * 2 + 1]);
        }
        __syncthreads();
    }

    // ---- LoRA epilogue: load operands into reused stage memory ----
    float* xas = (float*)sm;                 // [128][16]
    float* dBs = xas + 128 * 16;             // [16][132]
    {
        const float4* xp = (const float4*)(xA + (size_t)(b * TDIM + m0) * RLORA);
        for (int i = tid; i < 128 * 4; i += 256) ((float4*)xas)[i] = xp[i];
        const float* dBg = delta + ((size_t)b * 128 + (size_t)chunkB * RLORA) * CDIM;
        for (int i = tid; i < 16 * 128; i += 256) {
            int r = i >> 7, c = i & 127;
            dBs[r * 132 + c] = dBg[(size_t)r * CDIM + n0 + c];
        }
    }
    __syncthreads();

    int rbase = wm * 32 + (lane >> 2);
    int cbase = wn * 64 + (lane & 3) * 2;
#pragma unroll
    for (int r = 0; r < RLORA; r++) {
        float xv[4];
#pragma unroll
        for (int m8 = 0; m8 < 4; m8++) xv[m8] = xas[(rbase + m8 * 8) * 16 + r];
#pragma unroll
        for (int nt = 0; nt < 8; nt++) {
            float b0 = dBs[r * 132 + cbase + nt * 8];
            float b1 = dBs[r * 132 + cbase + nt * 8 + 1];
#pragma unroll
            for (int mt = 0; mt < 2; mt++) {
                acc[mt][nt][0] += xv[2 * mt] * b0;
                acc[mt][nt][1] += xv[2 * mt] * b1;
                acc[mt][nt][2] += xv[2 * mt + 1] * b0;
                acc[mt][nt][3] += xv[2 * mt + 1] * b1;
            }
        }
    }

    // ---- store ----
#pragma unroll
    for (int mt = 0; mt < 2; mt++) {
        int row = m0 + wm * 32 + mt * 16 + (lane >> 2);
#pragma unroll
        for (int nt = 0; nt < 8; nt++) {
            int col = n0 + wn * 64 + nt * 8 + (lane & 3) * 2;
            float* p0 = out + (size_t)(b * TDIM + row) * CDIM + col;
            float* p1 = out + (size_t)(b * TDIM + row + 8) * CDIM + col;
            *(float2*)p0 = make_float2(acc[mt][nt][0], acc[mt][nt][1]);
            *(float2*)p1 = make_float2(acc[mt][nt][2], acc[mt][nt][3]);
        }
    }
}

// ======================= RoPE + convert to head-major fp16 ===========
__global__ void rope_convert_kernel(const float* __restrict__ q,
                                    const float* __restrict__ k,
                                    __half* __restrict__ qhi,
                                    __half* __restrict__ qlo,
                                    __half* __restrict__ kh) {
    int idx = blockIdx.x * blockDim.x + threadIdx.x;
    if (idx >= BDIM * HDIM * TDIM * 32) return;
    int d2p = idx & 31;
    int t = (idx >> 5) & 1023;
    int h = (idx >> 15) & 15;
    int b = idx >> 19;
    const float SCALE = 0.08838834764831845f;

    size_t inb = ((size_t)(b * TDIM + t)) * CDIM + h * DHEAD + 2 * d2p;
    size_t ob = (((size_t)(b * HDIM + h)) * TDIM + t) * DHEAD + 2 * d2p;

    float rq[2][2], rk[2][2];
#pragma unroll
    for (int e = 0; e < 2; e++) {
        int d2 = 2 * d2p + e;
        float inv = powf(10000.0f, -(float)d2 * (1.0f / 64.0f));
        float s, c;
        sincosf((float)t * inv, &s, &c);
        float ql = q[inb + e], qh2 = q[inb + e + 64];
        rq[e][0] = (ql * c - qh2 * s) * SCALE;
        rq[e][1] = (qh2 * c + ql * s) * SCALE;
        float kl = k[inb + e], kh2 = k[inb + e + 64];
        rk[e][0] = kl * c - kh2 * s;
        rk[e][1] = kh2 * c + kl * s;
    }
#pragma unroll
    for (int half = 0; half < 2; half++) {
        float a = rq[0][half], bb = rq[1][half];
        uint32_t hi = pack_h(bb, a);
        __half2 hv = *(__half2*)&hi;
        float la = a - __half2float(hv.x);
        float lb = bb - __half2float(hv.y);
        uint32_t lo = pack_h(lb, la);
        *(uint32_t*)(qhi + ob + half * 64) = hi;
        *(uint32_t*)(qlo + ob + half * 64) = lo;

        *(uint32_t*)(kh + ob + half * 64) = pack_h(rk[1][half], rk[0][half]);
    }
}

// ======================= V transpose to [b,h,d,t] fp16 ===============
__global__ __launch_bounds__(256) void vtrans_kernel(const float* __restrict__ v,
                                                     __half* __restrict__ vth) {
    __shared__ float vs[64 * 132];
    int t0 = blockIdx.x * 64;
    int h = blockIdx.y, b = blockIdx.z;
    int tid = threadIdx.x;

#pragma unroll
    for (int it = 0; it < 8; it++) {
        int i4 = tid + it * 256;
        int row = i4 >> 5, c = (i4 & 31) << 2;
        float4 val = *(const float4*)(v + ((size_t)(b * TDIM + t0 + row)) * CDIM + h * DHEAD + c);
        *(float4*)&vs[row * 132 + c] = val;
    }
    __syncthreads();

    size_t obase = ((size_t)(b * HDIM + h)) * DHEAD * TDIM;
#pragma unroll
    for (int it = 0; it < 16; it++) {
        int j = tid + it * 256;
        int d = j >> 5, tp = j & 31;
        float a = vs[(2 * tp) * 132 + d];
        float bb = vs[(2 * tp + 1) * 132 + d];
        *(uint32_t*)(vth + obase + (size_t)d * TDIM + t0 + 2 * tp) = pack_h(bb, a);
    }
}

// ======================= tensor-core flash attention (fp16, 2-term) =======
#define AQ_STRIDE 272
#define KT_STRIDE 272
#define VT_STRIDE 144
#define AQ_TILE (64 * AQ_STRIDE)
#define KT_TILE (64 * KT_STRIDE)
#define VT_TILE (128 * VT_STRIDE)
#define KV_BUF (KT_TILE + VT_TILE)
#define ATTN_SMEM (2 * AQ_TILE + 2 * KV_BUF)   // 106496 -> 2 CTAs/SM

__global__ __launch_bounds__(128, 2)
void attn_tc_kernel(const __half* __restrict__ qhi,
                    const __half* __restrict__ qlo,
                    const __half* __restrict__ kh,
                    const __half* __restrict__ vth,
                    __half* __restrict__ yhi,
                    __half* __restrict__ ylo) {
    extern __shared__ char sm[];
    uint32_t sbase = smem_u32(sm);

    int tid = threadIdx.x;
    int warp = tid >> 5, lane = tid & 31;
    int b = blockIdx.z, h = blockIdx.y;
    int t0 = blockIdx.x * 64;

    const size_t qoff = (((size_t)(b * HDIM + h)) * TDIM + t0) * DHEAD;
    const size_t koff = ((size_t)(b * HDIM + h)) * TDIM * DHEAD;
    const size_t voff = ((size_t)(b * HDIM + h)) * DHEAD * TDIM;

#pragma unroll
    for (int it = 0; it < 16; it++) {
        int i = tid + it * 128;
        int tensor = i >> 10;
        int rem = i & 1023;
        int row = rem >> 4, ch = rem & 15;
        const __half* src = (tensor ? qlo : qhi) + qoff + (size_t)row * DHEAD + ch * 8;
        CP_ASYNC16(sbase + tensor * AQ_TILE + row * AQ_STRIDE + ch * 16, src);
    }
    CP_COMMIT();

    auto issue_kv = [&](int kt, int buf) {
        int s0 = kt * 64;
        uint32_t kb = sbase + 2 * AQ_TILE + buf * KV_BUF;
#pragma unroll
        for (int it = 0; it < 16; it++) {
            int i = tid + it * 128;
            if (i < 1024) {
                int row = i >> 4, ch = i & 15;
                const __half* src = kh + koff + (size_t)(s0 + row) * DHEAD + ch * 8;
                CP_ASYNC16(kb + row * KT_STRIDE + ch * 16, src);
            } else {
                int j = i - 1024;
                int row = j >> 3, ch = j & 7;
                const __half* src = vth + voff + (size_t)row * TDIM + s0 + ch * 8;
                CP_ASYNC16(kb + KT_TILE + row * VT_STRIDE + ch * 16, src);
            }
        }
        CP_COMMIT();
    };

    issue_kv(0, 0);

    int wrow = warp * 16;
    int qr = lane >> 2;
    int qc4 = (lane & 3) * 4;
    const float L2E = 1.4426950408889634f;

    float o[16][4];
#pragma unroll
    for (int nt = 0; nt < 16; nt++)
#pragma unroll
        for (int i = 0; i < 4; i++) o[nt][i] = 0.f;
    float m0 = -1e30f, m1 = -1e30f, l0 = 0.f, l1 = 0.f;

    for (int kt = 0; kt < TDIM / 64; kt++) {
        int buf = kt & 1;
        if (kt + 1 < TDIM / 64) {
            issue_kv(kt + 1, buf ^ 1);
            CP_WAIT(1);
        } else {
            CP_WAIT(0);
        }
        __syncthreads();

        uint32_t kvb = sbase + 2 * AQ_TILE + buf * KV_BUF;
        uint32_t k_s = kvb;
        uint32_t v_s = kvb + KT_TILE;

        float c[8][4];
#pragma unroll
        for (int nt = 0; nt < 8; nt++)
#pragma unroll
            for (int i = 0; i < 4; i++) c[nt][i] = 0.f;

#pragma unroll
        for (int ks = 0; ks < 8; ks++) {
            int kb = ks * 32;
            uint32_t ah[4], al[4], kfr[8][2];
            uint32_t qa = sbase + (wrow + qr) * AQ_STRIDE + kb + qc4;
            ah[0] = lds32(qa);           ah[1] = lds32(qa + 8 * AQ_STRIDE);
            ah[2] = lds32(qa + 16);      ah[3] = lds32(qa + 8 * AQ_STRIDE + 16);
            uint32_t qb = qa + AQ_TILE;
            al[0] = lds32(qb);           al[1] = lds32(qb + 8 * AQ_STRIDE);
            al[2] = lds32(qb + 16);      al[3] = lds32(qb + 8 * AQ_STRIDE + 16);
#pragma unroll
            for (int nt = 0; nt < 8; nt++) {
                uint32_t ka = k_s + (nt * 8 + qr) * KT_STRIDE + kb + qc4;
                kfr[nt][0] = lds32(ka); kfr[nt][1] = lds32(ka + 16);
            }
#pragma unroll
            for (int nt = 0; nt < 8; nt++)
                mma_f16(c[nt], ah, kfr[nt][0], kfr[nt][1]);
#pragma unroll
            for (int nt = 0; nt < 8; nt++)
                mma_f16(c[nt], al, kfr[nt][0], kfr[nt][1]);
        }

        float rm0 = -1e30f, rm1 = -1e30f;
#pragma unroll
        for (int nt = 0; nt < 8; nt++) {
            rm0 = fmaxf(rm0, fmaxf(c[nt][0], c[nt][1]));
            rm1 = fmaxf(rm1, fmaxf(c[nt][2], c[nt][3]));
        }
        rm0 = fmaxf(rm0, __shfl_xor_sync(0xffffffffu, rm0, 1));
        rm0 = fmaxf(rm0, __shfl_xor_sync(0xffffffffu, rm0, 2));
        rm1 = fmaxf(rm1, __shfl_xor_sync(0xffffffffu, rm1, 1));
        rm1 = fmaxf(rm1, __shfl_xor_sync(0xffffffffu, rm1, 2));
        float mn0 = fmaxf(m0, rm0), mn1 = fmaxf(m1, rm1);
        float cf0 = ex2((m0 - mn0) * L2E), cf1 = ex2((m1 - mn1) * L2E);
        m0 = mn0; m1 = mn1;
        float rs0 = 0.f, rs1 = 0.f;
#pragma unroll
        for (int nt = 0; nt < 8; nt++) {
            c[nt][0] = ex2((c[nt][0] - m0) * L2E);
            c[nt][1] = ex2((c[nt][1] - m0) * L2E);
            c[nt][2] = ex2((c[nt][2] - m1) * L2E);
            c[nt][3] = ex2((c[nt][3] - m1) * L2E);
            rs0 += c[nt][0] + c[nt][1];
            rs1 += c[nt][2] + c[nt][3];
        }
        rs0 += __shfl_xor_sync(0xffffffffu, rs0, 1);
        rs0 += __shfl_xor_sync(0xffffffffu, rs0, 2);
        rs1 += __shfl_xor_sync(0xffffffffu, rs1, 1);
        rs1 += __shfl_xor_sync(0xffffffffu, rs1, 2);
        l0 = l0 * cf0 + rs0;
        l1 = l1 * cf1 + rs1;
#pragma unroll
        for (int nt = 0; nt < 16; nt++) {
            o[nt][0] *= cf0; o[nt][1] *= cf0;
            o[nt][2] *= cf1; o[nt][3] *= cf1;
        }

        uint32_t phi[8][2], plo[8][2];
#pragma unroll
        for (int nt = 0; nt < 8; nt++) {
            uint32_t h0 = pack_h(c[nt][1], c[nt][0]);
            uint32_t h1 = pack_h(c[nt][3], c[nt][2]);
            phi[nt][0] = h0; phi[nt][1] = h1;
            __half2 v0 = *(__half2*)&h0;
            __half2 v1 = *(__half2*)&h1;
            float r0 = c[nt][0] - __half2float(v0.x);
            float r1 = c[nt][1] - __half2float(v0.y);
            float r2 = c[nt][2] - __half2float(v1.x);
            float r3 = c[nt][3] - __half2float(v1.y);
            plo[nt][0] = pack_h(r1, r0);
            plo[nt][1] = pack_h(r3, r2);
        }

#pragma unroll
        for (int ks2 = 0; ks2 < 4; ks2++) {
            uint32_t Ah[4] = {phi[2 * ks2][0], phi[2 * ks2][1],
                              phi[2 * ks2 + 1][0], phi[2 * ks2 + 1][1]};
            uint32_t Al[4] = {plo[2 * ks2][0], plo[2 * ks2][1],
                              plo[2 * ks2 + 1][0], plo[2 * ks2 + 1][1]};
            uint32_t vfr[16][2];
#pragma unroll
            for (int nt = 0; nt < 16; nt++) {
                uint32_t va = v_s + (nt * 8 + qr) * VT_STRIDE + ks2 * 32 + qc4;
                vfr[nt][0] = lds32(va); vfr[nt][1] = lds32(va + 16);
            }
#pragma unroll
            for (int nt = 0; nt < 16; nt++)
                mma_f16(o[nt], Ah, vfr[nt][0], vfr[nt][1]);
#pragma unroll
            for (int nt = 0; nt < 16; nt++)
                mma_f16(o[nt], Al, vfr[nt][0], vfr[nt][1]);
        }
        __syncthreads();
    }

    // ---- normalize + write y directly as fp16 hi/lo [B,T,C] ----
    float linv0 = 1.f / l0, linv1 = 1.f / l1;
    int row = t0 + wrow + qr;
#pragma unroll
    for (int nt = 0; nt < 16; nt++) {
        int col = h * DHEAD + nt * 8 + (lane & 3) * 2;
        size_t i0 = ((size_t)(b * TDIM + row)) * CDIM + col;
        size_t i1 = ((size_t)(b * TDIM + row + 8)) * CDIM + col;

        float v0 = o[nt][0] * linv0, v1 = o[nt][1] * linv0;
        uint32_t hw = pack_h(v1, v0);
        __half2 hh = *(__half2*)&hw;
        uint32_t lw = pack_h(v1 - __half2float(hh.y), v0 - __half2float(hh.x));
        *(uint32_t*)(yhi + i0) = hw;
        *(uint32_t*)(ylo + i0) = lw;

        float v2 = o[nt][2] * linv1, v3 = o[nt][3] * linv1;
        uint32_t hw2 = pack_h(v3, v2);
        __half2 hh2 = *(__half2*)&hw2;
        uint32_t lw2 = pack_h(v3 - __half2float(hh2.y), v2 - __half2float(hh2.x));
        *(uint32_t*)(yhi + i1) = hw2;
        *(uint32_t*)(ylo + i1) = lw2;
    }
}

// ---------------- host ----------------
extern "C" void kernel_launch(void* const* d_in, const int* in_sizes, int n_in,
                              void* d_out, int out_size) {
    const float* x     = (const float*)d_in[0];
    const float* delta = (const float*)d_in[1];
    const float* Wq    = (const float*)d_in[2];
    const float* Wk    = (const float*)d_in[3];
    const float* Wv    = (const float*)d_in[4];
    const float* Wo    = (const float*)d_in[5];
    float* out = (float*)d_out;

    float *qp, *kp, *vp, *xap;
    __half *xhi, *xlo, *yhi, *ylo, *wh;
    __half *qhi, *qlo, *kh, *vth;
    cudaGetSymbolAddress((void**)&qp, g_q);
    cudaGetSymbolAddress((void**)&kp, g_k);
    cudaGetSymbolAddress((void**)&vp, g_v);
    cudaGetSymbolAddress((void**)&xap, g_xa);
    cudaGetSymbolAddress((void**)&xhi, g_xhi);
    cudaGetSymbolAddress((void**)&xlo, g_xlo);
    cudaGetSymbolAddress((void**)&yhi, g_yhi);
    cudaGetSymbolAddress((void**)&ylo, g_ylo);
    cudaGetSymbolAddress((void**)&wh, g_wh);
    cudaGetSymbolAddress((void**)&qhi, g_qhi);
    cudaGetSymbolAddress((void**)&qlo, g_qlo);
    cudaGetSymbolAddress((void**)&kh, g_kh);
    cudaGetSymbolAddress((void**)&vth, g_vth);

    const int BT = BDIM * TDIM;
    float* xaq = xap;
    float* xak = xap + 1 * BT * RLORA;
    float* xav = xap + 2 * BT * RLORA;
    float* xao = xap + 3 * BT * RLORA;

    cudaFuncSetAttribute(gemm_tc_kernel, cudaFuncAttributeMaxDynamicSharedMemorySize, GEMM_SMEM);
    cudaFuncSetAttribute(attn_tc_kernel, cudaFuncAttributeMaxDynamicSharedMemorySize, ATTN_SMEM);

    const int WN = CDIM * CDIM;
    const int XN = BDIM * TDIM * CDIM;

    // Launch order chosen so launch #6 (ncu -s 5 -c 1) is a gemm_tc_kernel.
    split_kernel<<<(XN / 4 + 255) / 256, 256>>>(x, xhi, xlo, XN / 4);                 // 1
    round_all_kernel<<<dim3((WN / 4 + 255) / 256, 4), 256>>>(Wq, Wk, Wv, Wo, wh, WN / 4); // 2
    lowrank_kernel<<<BT / 32, 256>>>(x, delta, 0, 2, 4, 3, xaq, xak, xav);            // 3

    dim3 gg(CDIM / GBN, TDIM / GBM, BDIM);
    gemm_tc_kernel<<<gg, 256, GEMM_SMEM>>>(xhi, xlo, wh + 0 * (size_t)WN, xaq, delta, 1, qp); // 4
    gemm_tc_kernel<<<gg, 256, GEMM_SMEM>>>(xhi, xlo, wh + 1 * (size_t)WN, xak, delta, 3, kp); // 5
    gemm_tc_kernel<<<gg, 256, GEMM_SMEM>>>(xhi, xlo, wh + 2 * (size_t)WN, xav, delta, 5, vp); // 6 <- profiled

    int rc_n = BDIM * HDIM * TDIM * 32;
    rope_convert_kernel<<<(rc_n + 255) / 256, 256>>>(qp, kp, qhi, qlo, kh);           // 7
    vtrans_kernel<<<dim3(TDIM / 64, HDIM, BDIM), 256>>>(vp, vth);                     // 8

    attn_tc_kernel<<<dim3(TDIM / 64, HDIM, BDIM), 128, ATTN_SMEM>>>(
        qhi, qlo, kh, vth, yhi, ylo);                                                 // 9

    lowrank_h_kernel<<<BT / 32, 256>>>(yhi, ylo, delta, 6, xao);                      // 10
    gemm_tc_kernel<<<gg, 256, GEMM_SMEM>>>(yhi, ylo, wh + 3 * (size_t)WN, xao, delta, 7, out); // 11
}